// round 5
// baseline (speedup 1.0000x reference)
#include <cuda_runtime.h>
#include <cstdint>

// Problem constants: pred/target [8,3,512,512] fp32, output scalar fp32.
#define BATCH   8
#define CHAN    3
#define HW      262144              // 512*512
#define NB      16                  // coarse bins
#define NF      1024                // fine bins
#define NSLICE  48                  // 2 tensors * 8 * 3
#define SPLITS  18                  // chunks per batch
#define CHUNK   14568               // ceil(HW/18) rounded to mult of 8; 18*14568 >= HW

// Per-pixel fixed point: u = (uint)(x * 16384)  (exact: x in [0,1))
//   fine bin j = u >> 4, sub-bin delta16 = u & 15.
// Smem cell (32-bit): count in bits[18:32), sum(delta16) in bits[0:18).
//   per block per channel-tensor <= 14568 px: count < 2^14, sum <= 14568*15 < 2^18.
// Global cell (64-bit): count in high 32, sum(delta16) in low 32 (<= 3.9M). No carry.

__device__ unsigned long long g_fine[NSLICE][NF];   // 384 KB scratch (zero at load,
                                                    // re-zeroed by reconstruct each call)
__device__ float              g_hist[NSLICE][NB];   // reconstructed coarse hists
__device__ unsigned int       g_ctr;                // completion ticket (self-resetting)

// ---------------------------------------------------------------------------
// Kernel 1: fused mask + fine histogram.
// grid = BATCH * SPLITS = 144 blocks, 256 threads, 24 KB smem.
// Each block: one batch, one pixel chunk, BOTH tensors, ALL 3 channels.
// Mask (mean(target,ch) > 0.4) computed inline from the target loads.
// ---------------------------------------------------------------------------
__device__ __forceinline__ void fine_add(unsigned int* sh, float x, bool m) {
    if (m) {
        unsigned int u = (unsigned int)(x * 16384.0f);   // exact fixed point
        atomicAdd(&sh[u >> 4], 0x40000u | (u & 15u));
    }
}

__global__ __launch_bounds__(256) void hist_kernel(const float* __restrict__ pred,
                                                   const float* __restrict__ target) {
    __shared__ unsigned int sh[6][NF];                   // [ch][bin] x {pred:0-2, target:3-5}
    int b     = blockIdx.x / SPLITS;
    int chunk = blockIdx.x % SPLITS;

    unsigned int* shf = &sh[0][0];
    #pragma unroll
    for (int j = threadIdx.x; j < 6 * NF; j += 256) shf[j] = 0u;
    __syncthreads();

    const float* tb = target + (size_t)b * CHAN * HW;
    const float* pb = pred   + (size_t)b * CHAN * HW;

    int start = chunk * CHUNK;
    int end   = min(start + CHUNK, HW);
    for (int i = start + (int)threadIdx.x * 4; i < end; i += 256 * 4) {
        float4 t0 = *(const float4*)(tb + i);
        float4 t1 = *(const float4*)(tb + HW + i);
        float4 t2 = *(const float4*)(tb + 2 * HW + i);
        bool mx = (t0.x + t1.x) + t2.x > 1.2f;           // mean > 0.4
        bool my = (t0.y + t1.y) + t2.y > 1.2f;
        bool mz = (t0.z + t1.z) + t2.z > 1.2f;
        bool mw = (t0.w + t1.w) + t2.w > 1.2f;

        fine_add(sh[3], t0.x, mx); fine_add(sh[3], t0.y, my);
        fine_add(sh[3], t0.z, mz); fine_add(sh[3], t0.w, mw);
        fine_add(sh[4], t1.x, mx); fine_add(sh[4], t1.y, my);
        fine_add(sh[4], t1.z, mz); fine_add(sh[4], t1.w, mw);
        fine_add(sh[5], t2.x, mx); fine_add(sh[5], t2.y, my);
        fine_add(sh[5], t2.z, mz); fine_add(sh[5], t2.w, mw);

        float4 p0 = *(const float4*)(pb + i);
        float4 p1 = *(const float4*)(pb + HW + i);
        float4 p2 = *(const float4*)(pb + 2 * HW + i);
        fine_add(sh[0], p0.x, mx); fine_add(sh[0], p0.y, my);
        fine_add(sh[0], p0.z, mz); fine_add(sh[0], p0.w, mw);
        fine_add(sh[1], p1.x, mx); fine_add(sh[1], p1.y, my);
        fine_add(sh[1], p1.z, mz); fine_add(sh[1], p1.w, mw);
        fine_add(sh[2], p2.x, mx); fine_add(sh[2], p2.y, my);
        fine_add(sh[2], p2.z, mz); fine_add(sh[2], p2.w, mw);
    }
    __syncthreads();

    // Flush: slice = tensor*24 + b*3 + ch ; local layout ct = tensor*3 + ch
    #pragma unroll
    for (int idx = threadIdx.x; idx < 6 * NF; idx += 256) {
        unsigned int v = shf[idx];
        if (v) {
            int ct = idx >> 10;                          // 0..5 (0-2 pred, 3-5 target)
            int j  = idx & (NF - 1);
            int t  = ct >= 3;
            int ch = ct - t * 3;
            atomicAdd(&g_fine[t * 24 + b * 3 + ch][j],
                      ((unsigned long long)(v >> 18) << 32) |
                       (unsigned long long)(v & 0x3FFFFu));
        }
    }
}

// ---------------------------------------------------------------------------
// Kernel 2 (fused): reconstruct 16-bin soft histograms (1st-order Taylor,
// Gaussian weights computed inline) + last block computes the final loss.
// Also re-zeros g_fine and the ticket so the next call starts clean.
// grid = 48 (one block per slice), 512 threads = 16 bins x 32 lanes.
// ---------------------------------------------------------------------------
__global__ __launch_bounds__(512) void reconstruct_final_kernel(float* __restrict__ out) {
    __shared__ float sn [NF];                            // counts
    __shared__ float sdv[NF];                            // sum(x_i - c_j), scaled
    __shared__ bool  amLast;
    __shared__ double part[24];

    int s   = blockIdx.x;
    int tid = threadIdx.x;

    unsigned long long* gf = g_fine[s];
    #pragma unroll
    for (int j = tid; j < NF; j += 512) {
        unsigned long long v = gf[j];
        gf[j] = 0ULL;                                    // self-clean for next call
        float n  = (float)(unsigned)(v >> 32);
        float sd = (float)(unsigned)(v & 0xFFFFFFFFu);   // sum(delta16)
        sn [j] = n;
        // sum(delta) ~= (sum(delta16) + 0.5 n)/16 ; sdv = (sum(delta) - n/2) / NF
        sdv[j] = (sd * 0.0625f - n * 0.46875f) * (1.0f / (float)NF);
    }
    __syncthreads();

    int k    = tid >> 5;                                 // one warp per coarse bin
    int lane = tid & 31;
    float ck = (float)k * (1.0f / 15.0f);                // linspace(0,1,16)
    float acc = 0.0f;
    #pragma unroll 4
    for (int j0 = 0; j0 < NF; j0 += 32) {
        int j = j0 + lane;
        float cj = ((float)j + 0.5f) * (1.0f / (float)NF);
        float d  = cj - ck;
        float w  = __expf(-128.0f * d * d);              // inv_two_sigma2 = 128
        float wp = -256.0f * d * w;
        acc = fmaf(sn[j], w, fmaf(sdv[j], wp, acc));
    }
    #pragma unroll
    for (int off = 16; off > 0; off >>= 1)
        acc += __shfl_xor_sync(0xffffffffu, acc, off);
    if (lane == 0) g_hist[s][k] = acc;
    __syncthreads();

    // ticket: last block to finish computes the loss
    if (tid == 0) {
        __threadfence();
        unsigned int t = atomicAdd(&g_ctr, 1u);
        amLast = (t == (unsigned)(gridDim.x - 1));
        if (amLast) g_ctr = 0u;                          // reset for next call
    }
    __syncthreads();
    if (!amLast) return;

    if (tid < 24) {
        const float* hp = g_hist[tid];                   // pred slice bc
        const float* ht = g_hist[24 + tid];              // target slice bc
        double s0 = 0.0, s1 = 0.0;
        #pragma unroll
        for (int kk = 0; kk < NB; kk++) { s0 += (double)hp[kk]; s1 += (double)ht[kk]; }
        double i0 = 1.0 / (s0 + 1e-7);
        double i1 = 1.0 / (s1 + 1e-7);
        double a = 0.0;
        #pragma unroll
        for (int kk = 0; kk < NB; kk++)
            a += fabs((double)hp[kk] * i0 - (double)ht[kk] * i1);
        part[tid] = a;
    }
    __syncthreads();
    if (tid == 0) {
        double ssum = 0.0;
        #pragma unroll
        for (int i = 0; i < 24; i++) ssum += part[i];
        *out = (float)(ssum * (1.0 / 384.0));
    }
}

// ---------------------------------------------------------------------------
extern "C" void kernel_launch(void* const* d_in, const int* in_sizes, int n_in,
                              void* d_out, int out_size) {
    const float* pred   = (const float*)d_in[0];
    const float* target = (const float*)d_in[1];
    float* out = (float*)d_out;

    hist_kernel<<<BATCH * SPLITS, 256>>>(pred, target);
    reconstruct_final_kernel<<<NSLICE, 512>>>(out);
}

// round 6
// speedup vs baseline: 1.5151x; 1.5151x over previous
#include <cuda_runtime.h>
#include <cstdint>

// Problem constants: pred/target [8,3,512,512] fp32, output scalar fp32.
#define BATCH   8
#define CHAN    3
#define HW      262144              // 512*512
#define NB      16                  // coarse bins
#define NF      1024                // fine bins
#define NSLICE  48                  // 2 tensors * 8 * 3
#define SPLITS  18                  // chunks per batch
#define CHUNK   14568               // ceil(HW/18) rounded to mult of 8; 18*14568 >= HW
#define HIST_THREADS 1024

// Per-pixel fixed point: u = (uint)(x * 16384)  (exact: x in [0,1))
//   fine bin j = u >> 4, sub-bin delta16 = u & 15.
// Smem cell (32-bit): count in bits[18:32), sum(delta16) in bits[0:18).
//   per block per channel-tensor <= 14568 px: count < 2^14, sum <= 14568*15 < 2^18.
// Global cell (64-bit): count in high 32, sum(delta16) in low 32 (<= 3.9M). No carry.

__device__ unsigned long long g_fine[NSLICE][NF];   // 384 KB scratch (zero at load,
                                                    // re-zeroed by reconstruct each call)
__device__ float              g_w [NB][NF];         // Gaussian weight table (rebuilt per call)
__device__ float              g_wp[NB][NF];         // derivative table
__device__ float              g_hist[NSLICE][NB];   // reconstructed coarse hists
__device__ unsigned int       g_ctr;                // completion ticket (self-resetting)

// ---------------------------------------------------------------------------
// Kernel 1: fused mask + fine histogram (+ table build in first 16 blocks).
// grid = BATCH * SPLITS = 144 blocks, 1024 threads, 24 KB smem.
// Each block: one batch, one pixel chunk, BOTH tensors, ALL 3 channels.
// Mask (mean(target,ch) > 0.4) computed inline from the target loads.
// ---------------------------------------------------------------------------
__device__ __forceinline__ void fine_add(unsigned int* sh, float x, bool m) {
    if (m) {
        unsigned int u = (unsigned int)(x * 16384.0f);   // exact fixed point
        atomicAdd(&sh[u >> 4], 0x40000u | (u & 15u));
    }
}

__global__ __launch_bounds__(HIST_THREADS) void hist_kernel(const float* __restrict__ pred,
                                                            const float* __restrict__ target) {
    __shared__ unsigned int sh[6][NF];                   // [ch][bin] x {pred:0-2, target:3-5}
    int b     = blockIdx.x / SPLITS;
    int chunk = blockIdx.x % SPLITS;

    // Rebuild Gaussian tables each call (blocks 0..15, 1024 entries each).
    // Off the hot path; reconstruct launch consumes them after this kernel ends.
    if (blockIdx.x < 16) {
        int idx = blockIdx.x * HIST_THREADS + threadIdx.x;   // 0..16383
        int k = idx >> 10;
        int j = idx & (NF - 1);
        float ck = (float)k * (1.0f / 15.0f);            // linspace(0,1,16)
        float cj = ((float)j + 0.5f) * (1.0f / (float)NF);
        float d  = cj - ck;
        float w  = expf(-d * d * 128.0f);                // inv_two_sigma2 = 128
        g_w [k][j] = w;
        g_wp[k][j] = -256.0f * d * w;
    }

    unsigned int* shf = &sh[0][0];
    #pragma unroll
    for (int j = threadIdx.x; j < 6 * NF; j += HIST_THREADS) shf[j] = 0u;
    __syncthreads();

    const float* tb = target + (size_t)b * CHAN * HW;
    const float* pb = pred   + (size_t)b * CHAN * HW;

    int start = chunk * CHUNK;
    int end   = min(start + CHUNK, HW);
    for (int i = start + (int)threadIdx.x * 4; i < end; i += HIST_THREADS * 4) {
        // front-batch all six 16B loads (MLP=6) before the atomic burst
        float4 t0 = *(const float4*)(tb + i);
        float4 t1 = *(const float4*)(tb + HW + i);
        float4 t2 = *(const float4*)(tb + 2 * HW + i);
        float4 p0 = *(const float4*)(pb + i);
        float4 p1 = *(const float4*)(pb + HW + i);
        float4 p2 = *(const float4*)(pb + 2 * HW + i);

        bool mx = (t0.x + t1.x) + t2.x > 1.2f;           // mean > 0.4
        bool my = (t0.y + t1.y) + t2.y > 1.2f;
        bool mz = (t0.z + t1.z) + t2.z > 1.2f;
        bool mw = (t0.w + t1.w) + t2.w > 1.2f;

        fine_add(sh[0], p0.x, mx); fine_add(sh[0], p0.y, my);
        fine_add(sh[0], p0.z, mz); fine_add(sh[0], p0.w, mw);
        fine_add(sh[1], p1.x, mx); fine_add(sh[1], p1.y, my);
        fine_add(sh[1], p1.z, mz); fine_add(sh[1], p1.w, mw);
        fine_add(sh[2], p2.x, mx); fine_add(sh[2], p2.y, my);
        fine_add(sh[2], p2.z, mz); fine_add(sh[2], p2.w, mw);
        fine_add(sh[3], t0.x, mx); fine_add(sh[3], t0.y, my);
        fine_add(sh[3], t0.z, mz); fine_add(sh[3], t0.w, mw);
        fine_add(sh[4], t1.x, mx); fine_add(sh[4], t1.y, my);
        fine_add(sh[4], t1.z, mz); fine_add(sh[4], t1.w, mw);
        fine_add(sh[5], t2.x, mx); fine_add(sh[5], t2.y, my);
        fine_add(sh[5], t2.z, mz); fine_add(sh[5], t2.w, mw);
    }
    __syncthreads();

    // Flush: slice = tensor*24 + b*3 + ch ; local layout ct = tensor*3 + ch
    #pragma unroll
    for (int idx = threadIdx.x; idx < 6 * NF; idx += HIST_THREADS) {
        unsigned int v = shf[idx];
        if (v) {
            int ct = idx >> 10;                          // 0..5 (0-2 pred, 3-5 target)
            int j  = idx & (NF - 1);
            int t  = ct >= 3;
            int ch = ct - t * 3;
            atomicAdd(&g_fine[t * 24 + b * 3 + ch][j],
                      ((unsigned long long)(v >> 18) << 32) |
                       (unsigned long long)(v & 0x3FFFFu));
        }
    }
}

// ---------------------------------------------------------------------------
// Kernel 2 (fused): reconstruct 16-bin soft histograms (1st-order Taylor,
// table-based Gaussian weights) + last block computes the final loss.
// Re-zeros g_fine and the ticket so the next call starts clean.
// grid = 48 (one block per slice), 512 threads = 16 bins x 32 lanes.
// ---------------------------------------------------------------------------
__global__ __launch_bounds__(512) void reconstruct_final_kernel(float* __restrict__ out) {
    __shared__ float sn [NF];                            // counts
    __shared__ float sdv[NF];                            // sum(x_i - c_j), scaled
    __shared__ bool  amLast;
    __shared__ double part[24];

    int s   = blockIdx.x;
    int tid = threadIdx.x;

    unsigned long long* gf = g_fine[s];
    #pragma unroll
    for (int j = tid; j < NF; j += 512) {
        unsigned long long v = gf[j];
        gf[j] = 0ULL;                                    // self-clean for next call
        float n  = (float)(unsigned)(v >> 32);
        float sd = (float)(unsigned)(v & 0xFFFFFFFFu);   // sum(delta16)
        sn [j] = n;
        // sum(delta) ~= (sum(delta16) + 0.5 n)/16 ; sdv = (sum(delta) - n/2) / NF
        sdv[j] = (sd * 0.0625f - n * 0.46875f) * (1.0f / (float)NF);
    }
    __syncthreads();

    int k    = tid >> 5;                                 // one warp per coarse bin
    int lane = tid & 31;
    const float* wr  = g_w [k];
    const float* wpr = g_wp[k];
    float a0 = 0.0f, a1 = 0.0f;
    #pragma unroll
    for (int j0 = 0; j0 < NF; j0 += 64) {
        int ja = j0 + lane, jb = j0 + 32 + lane;
        a0 = fmaf(sn[ja], __ldg(&wr[ja]), fmaf(sdv[ja], __ldg(&wpr[ja]), a0));
        a1 = fmaf(sn[jb], __ldg(&wr[jb]), fmaf(sdv[jb], __ldg(&wpr[jb]), a1));
    }
    float acc = a0 + a1;
    #pragma unroll
    for (int off = 16; off > 0; off >>= 1)
        acc += __shfl_xor_sync(0xffffffffu, acc, off);
    if (lane == 0) g_hist[s][k] = acc;
    __syncthreads();

    // ticket: last block to finish computes the loss
    if (tid == 0) {
        __threadfence();
        unsigned int t = atomicAdd(&g_ctr, 1u);
        amLast = (t == (unsigned)(gridDim.x - 1));
        if (amLast) g_ctr = 0u;                          // reset for next call
    }
    __syncthreads();
    if (!amLast) return;

    if (tid < 24) {
        const float* hp = g_hist[tid];                   // pred slice bc
        const float* ht = g_hist[24 + tid];              // target slice bc
        double s0 = 0.0, s1 = 0.0;
        #pragma unroll
        for (int kk = 0; kk < NB; kk++) { s0 += (double)hp[kk]; s1 += (double)ht[kk]; }
        double i0 = 1.0 / (s0 + 1e-7);
        double i1 = 1.0 / (s1 + 1e-7);
        double a = 0.0;
        #pragma unroll
        for (int kk = 0; kk < NB; kk++)
            a += fabs((double)hp[kk] * i0 - (double)ht[kk] * i1);
        part[tid] = a;
    }
    __syncthreads();
    if (tid == 0) {
        double ssum = 0.0;
        #pragma unroll
        for (int i = 0; i < 24; i++) ssum += part[i];
        *out = (float)(ssum * (1.0 / 384.0));
    }
}

// ---------------------------------------------------------------------------
extern "C" void kernel_launch(void* const* d_in, const int* in_sizes, int n_in,
                              void* d_out, int out_size) {
    const float* pred   = (const float*)d_in[0];
    const float* target = (const float*)d_in[1];
    float* out = (float*)d_out;

    hist_kernel<<<BATCH * SPLITS, HIST_THREADS>>>(pred, target);
    reconstruct_final_kernel<<<NSLICE, 512>>>(out);
}

// round 7
// speedup vs baseline: 1.6611x; 1.0964x over previous
#include <cuda_runtime.h>
#include <cstdint>

// Problem constants: pred/target [8,3,512,512] fp32, output scalar fp32.
#define BATCH   8
#define CHAN    3
#define HW      262144              // 512*512
#define NB      16                  // coarse bins
#define NFS     1024                // smem fine bins (atomic spread)
#define NFC     256                 // reconstruction fine bins (global)
#define NSLICE  48                  // 2 tensors * 8 * 3
#define SPLITS  18                  // chunks per batch
#define CHUNK   14568               // ceil(HW/18) rounded; 18*14568 >= HW
#define HIST_THREADS 1024

// Per-pixel fixed point: u = (uint)(x * 16384)  (exact: x in [0,1))
// Smem bin j10 = u >> 4 (1024 bins), stored sub-delta16 = u & 15.
// Smem cell (32-bit): count in bits[18:32), sum(delta16) in bits[0:18).
//   per block per channel-tensor <= 14568 px: count < 2^14, sum <= 14568*15 < 2^18.
// Global bins jc = u >> 6 (256 bins), delta64 = u & 63 = (j10&3)*16 + delta16.
// Global cell (64-bit): count in high 32, sum(delta64) in low 32
//   (<= 262144*63 = 16.5M < 2^32 per slice -> no carry).

__device__ unsigned long long g_fine[NSLICE][NFC];  // 96 KB scratch (zero at load,
                                                    // re-zeroed by reconstruct)
__device__ float              g_w [NB][NFC];        // Gaussian weight table
__device__ float              g_wp[NB][NFC];        // derivative table
__device__ float              g_hist[NSLICE][NB];   // reconstructed coarse hists
__device__ unsigned int       g_ctr;                // completion ticket (self-resetting)

// ---------------------------------------------------------------------------
// Kernel 1: fused mask + fine histogram (+ table build in blocks 0..3).
// grid = BATCH * SPLITS = 144 blocks, 1024 threads, 24 KB smem.
// ---------------------------------------------------------------------------
__device__ __forceinline__ void fine_add(unsigned int* sh, float x, bool m) {
    if (m) {
        unsigned int u = (unsigned int)(x * 16384.0f);   // exact fixed point
        atomicAdd(&sh[u >> 4], 0x40000u | (u & 15u));
    }
}

__global__ __launch_bounds__(HIST_THREADS) void hist_kernel(const float* __restrict__ pred,
                                                            const float* __restrict__ target) {
    __shared__ unsigned int sh[6][NFS];                  // [ct][bin], ct: pred 0-2, target 3-5
    int b     = blockIdx.x / SPLITS;
    int chunk = blockIdx.x % SPLITS;

    // Rebuild Gaussian tables each call (blocks 0..3 cover 16x256 entries).
    if (blockIdx.x < 4) {
        int idx = blockIdx.x * HIST_THREADS + threadIdx.x;   // 0..4095
        int k = idx >> 8;
        int j = idx & (NFC - 1);
        float ck = (float)k * (1.0f / 15.0f);            // linspace(0,1,16)
        float cj = ((float)j + 0.5f) * (1.0f / (float)NFC);
        float d  = cj - ck;
        float w  = expf(-d * d * 128.0f);                // inv_two_sigma2 = 128
        g_w [k][j] = w;
        g_wp[k][j] = -256.0f * d * w;
    }

    unsigned int* shf = &sh[0][0];
    #pragma unroll
    for (int j = threadIdx.x; j < 6 * NFS; j += HIST_THREADS) shf[j] = 0u;
    __syncthreads();

    const float* tb = target + (size_t)b * CHAN * HW;
    const float* pb = pred   + (size_t)b * CHAN * HW;

    int start = chunk * CHUNK;
    int end   = min(start + CHUNK, HW);
    for (int i = start + (int)threadIdx.x * 4; i < end; i += HIST_THREADS * 4) {
        // front-batch all six 16B loads (MLP=6) before the atomic burst
        float4 t0 = *(const float4*)(tb + i);
        float4 t1 = *(const float4*)(tb + HW + i);
        float4 t2 = *(const float4*)(tb + 2 * HW + i);
        float4 p0 = *(const float4*)(pb + i);
        float4 p1 = *(const float4*)(pb + HW + i);
        float4 p2 = *(const float4*)(pb + 2 * HW + i);

        bool mx = (t0.x + t1.x) + t2.x > 1.2f;           // mean > 0.4
        bool my = (t0.y + t1.y) + t2.y > 1.2f;
        bool mz = (t0.z + t1.z) + t2.z > 1.2f;
        bool mw = (t0.w + t1.w) + t2.w > 1.2f;

        fine_add(sh[0], p0.x, mx); fine_add(sh[0], p0.y, my);
        fine_add(sh[0], p0.z, mz); fine_add(sh[0], p0.w, mw);
        fine_add(sh[1], p1.x, mx); fine_add(sh[1], p1.y, my);
        fine_add(sh[1], p1.z, mz); fine_add(sh[1], p1.w, mw);
        fine_add(sh[2], p2.x, mx); fine_add(sh[2], p2.y, my);
        fine_add(sh[2], p2.z, mz); fine_add(sh[2], p2.w, mw);
        fine_add(sh[3], t0.x, mx); fine_add(sh[3], t0.y, my);
        fine_add(sh[3], t0.z, mz); fine_add(sh[3], t0.w, mw);
        fine_add(sh[4], t1.x, mx); fine_add(sh[4], t1.y, my);
        fine_add(sh[4], t1.z, mz); fine_add(sh[4], t1.w, mw);
        fine_add(sh[5], t2.x, mx); fine_add(sh[5], t2.y, my);
        fine_add(sh[5], t2.z, mz); fine_add(sh[5], t2.w, mw);
    }
    __syncthreads();

    // Flush with 4:1 fold to 256 global bins.  idx -> (ct, jc).
    #pragma unroll
    for (int idx = threadIdx.x; idx < 6 * NFC; idx += HIST_THREADS) {
        int ct = idx >> 8;                               // 0..5 (0-2 pred, 3-5 target)
        int jc = idx & (NFC - 1);
        const unsigned int* cell = &sh[ct][jc << 2];
        unsigned long long cnt = 0, sd = 0;
        #pragma unroll
        for (int r = 0; r < 4; r++) {
            unsigned int v = cell[r];
            unsigned long long c = v >> 18;
            sd  += (unsigned long long)(v & 0x3FFFFu) + 16ull * (unsigned)r * c;
            cnt += c;
        }
        if (cnt) {
            int t  = ct >= 3;
            int ch = ct - t * 3;
            atomicAdd(&g_fine[t * 24 + b * 3 + ch][jc], (cnt << 32) | sd);
        }
    }
}

// ---------------------------------------------------------------------------
// Kernel 2 (fused): reconstruct 16-bin soft histograms (1st-order Taylor,
// table-based weights) + last block computes the final loss.
// Re-zeros g_fine and the ticket.  grid = 48, 512 threads = 16 bins x 32 lanes.
// ---------------------------------------------------------------------------
__global__ __launch_bounds__(512) void reconstruct_final_kernel(float* __restrict__ out) {
    __shared__ float sn [NFC];                           // counts
    __shared__ float sdv[NFC];                           // sum(x_i - c_j), scaled
    __shared__ bool  amLast;
    __shared__ double part[24];

    int s   = blockIdx.x;
    int tid = threadIdx.x;

    unsigned long long* gf = g_fine[s];
    if (tid < NFC) {
        unsigned long long v = gf[tid];
        gf[tid] = 0ULL;                                  // self-clean for next call
        float n  = (float)(unsigned)(v >> 32);
        float sd = (float)(unsigned)(v & 0xFFFFFFFFu);   // sum(delta64)
        sn [tid] = n;
        // sum(delta) ~= (sum(delta64) + 0.5 n)/64 ; sdv = (sum(delta) - n/2) / NFC
        sdv[tid] = (sd * 0.015625f - n * 0.4921875f) * (1.0f / (float)NFC);
    }
    __syncthreads();

    int k    = tid >> 5;                                 // one warp per coarse bin
    int lane = tid & 31;
    const float* wr  = g_w [k];
    const float* wpr = g_wp[k];
    float a0 = 0.0f, a1 = 0.0f;
    #pragma unroll
    for (int j0 = 0; j0 < NFC; j0 += 64) {
        int ja = j0 + lane, jb = j0 + 32 + lane;
        a0 = fmaf(sn[ja], __ldg(&wr[ja]), fmaf(sdv[ja], __ldg(&wpr[ja]), a0));
        a1 = fmaf(sn[jb], __ldg(&wr[jb]), fmaf(sdv[jb], __ldg(&wpr[jb]), a1));
    }
    float acc = a0 + a1;
    #pragma unroll
    for (int off = 16; off > 0; off >>= 1)
        acc += __shfl_xor_sync(0xffffffffu, acc, off);
    if (lane == 0) g_hist[s][k] = acc;
    __syncthreads();

    // ticket: last block to finish computes the loss
    if (tid == 0) {
        __threadfence();
        unsigned int t = atomicAdd(&g_ctr, 1u);
        amLast = (t == (unsigned)(gridDim.x - 1));
        if (amLast) g_ctr = 0u;                          // reset for next call
    }
    __syncthreads();
    if (!amLast) return;

    if (tid < 24) {
        const float* hp = g_hist[tid];                   // pred slice bc
        const float* ht = g_hist[24 + tid];              // target slice bc
        double s0 = 0.0, s1 = 0.0;
        #pragma unroll
        for (int kk = 0; kk < NB; kk++) { s0 += (double)hp[kk]; s1 += (double)ht[kk]; }
        double i0 = 1.0 / (s0 + 1e-7);
        double i1 = 1.0 / (s1 + 1e-7);
        double a = 0.0;
        #pragma unroll
        for (int kk = 0; kk < NB; kk++)
            a += fabs((double)hp[kk] * i0 - (double)ht[kk] * i1);
        part[tid] = a;
    }
    __syncthreads();
    if (tid == 0) {
        double ssum = 0.0;
        #pragma unroll
        for (int i = 0; i < 24; i++) ssum += part[i];
        *out = (float)(ssum * (1.0 / 384.0));
    }
}

// ---------------------------------------------------------------------------
extern "C" void kernel_launch(void* const* d_in, const int* in_sizes, int n_in,
                              void* d_out, int out_size) {
    const float* pred   = (const float*)d_in[0];
    const float* target = (const float*)d_in[1];
    float* out = (float*)d_out;

    hist_kernel<<<BATCH * SPLITS, HIST_THREADS>>>(pred, target);
    reconstruct_final_kernel<<<NSLICE, 512>>>(out);
}

// round 8
// speedup vs baseline: 1.8663x; 1.1235x over previous
#include <cuda_runtime.h>
#include <cstdint>

// Problem constants: pred/target [8,3,512,512] fp32, output scalar fp32.
#define BATCH   8
#define CHAN    3
#define HW      262144              // 512*512
#define NB      16                  // coarse bins
#define NFS     1024                // smem fine bins (atomic spread)
#define NFC     256                 // reconstruction fine bins (global)
#define NSLICE  48                  // 2 tensors * 8 * 3
#define SPLITS  18                  // chunks per batch
#define CHUNK   14568               // ceil(HW/18) rounded; 18*14568 >= HW
#define HIST_THREADS 1024

// Per-pixel fixed point: u = (uint)(x * 16384)  (exact: x in [0,1))
// Smem bin j10 = u >> 4 (1024 bins), stored sub-delta16 = u & 15.
// Smem cell (32-bit): count in bits[18:32), sum(delta16) in bits[0:18).
//   per block per channel-tensor <= 14568 px: count < 2^14, sum <= 14568*15 < 2^18.
// Global bins jc = u >> 6 (256 bins), delta64 = u & 63 = (j10&3)*16 + delta16.
// Global cell (64-bit): count in high 32, sum(delta64) in low 32
//   (<= 262144*63 = 16.5M < 2^32 per slice -> no carry).

__device__ unsigned long long g_fine[NSLICE][NFC];  // 96 KB scratch (zero at load,
                                                    // re-zeroed by final_kernel)
__device__ float              g_w [NB][NFC];        // Gaussian weight table
__device__ float              g_wp[NB][NFC];        // derivative table
__device__ float              g_hist[NSLICE][NB];   // reconstructed coarse hists

// ---------------------------------------------------------------------------
// Kernel 1: fused mask + fine histogram (+ table build in blocks 0..3).
// grid = BATCH * SPLITS = 144 blocks, 1024 threads, 24 KB smem.
// ---------------------------------------------------------------------------
__device__ __forceinline__ void fine_add(unsigned int* sh, float x, bool m) {
    if (m) {
        unsigned int u = (unsigned int)(x * 16384.0f);   // exact fixed point
        atomicAdd(&sh[u >> 4], 0x40000u | (u & 15u));
    }
}

__global__ __launch_bounds__(HIST_THREADS) void hist_kernel(const float* __restrict__ pred,
                                                            const float* __restrict__ target) {
    __shared__ unsigned int sh[6][NFS];                  // [ct][bin], ct: pred 0-2, target 3-5
    int b     = blockIdx.x / SPLITS;
    int chunk = blockIdx.x % SPLITS;

    // Rebuild Gaussian tables each call (blocks 0..3 cover 16x256 entries).
    if (blockIdx.x < 4) {
        int idx = blockIdx.x * HIST_THREADS + threadIdx.x;   // 0..4095
        int k = idx >> 8;
        int j = idx & (NFC - 1);
        float ck = (float)k * (1.0f / 15.0f);            // linspace(0,1,16)
        float cj = ((float)j + 0.5f) * (1.0f / (float)NFC);
        float d  = cj - ck;
        float w  = expf(-d * d * 128.0f);                // inv_two_sigma2 = 128
        g_w [k][j] = w;
        g_wp[k][j] = -256.0f * d * w;
    }

    unsigned int* shf = &sh[0][0];
    #pragma unroll
    for (int j = threadIdx.x; j < 6 * NFS; j += HIST_THREADS) shf[j] = 0u;
    __syncthreads();

    const float* tb = target + (size_t)b * CHAN * HW;
    const float* pb = pred   + (size_t)b * CHAN * HW;

    int start = chunk * CHUNK;
    int end   = min(start + CHUNK, HW);
    for (int i = start + (int)threadIdx.x * 4; i < end; i += HIST_THREADS * 4) {
        // front-batch all six 16B loads (MLP=6) before the atomic burst
        float4 t0 = *(const float4*)(tb + i);
        float4 t1 = *(const float4*)(tb + HW + i);
        float4 t2 = *(const float4*)(tb + 2 * HW + i);
        float4 p0 = *(const float4*)(pb + i);
        float4 p1 = *(const float4*)(pb + HW + i);
        float4 p2 = *(const float4*)(pb + 2 * HW + i);

        bool mx = (t0.x + t1.x) + t2.x > 1.2f;           // mean > 0.4
        bool my = (t0.y + t1.y) + t2.y > 1.2f;
        bool mz = (t0.z + t1.z) + t2.z > 1.2f;
        bool mw = (t0.w + t1.w) + t2.w > 1.2f;

        fine_add(sh[0], p0.x, mx); fine_add(sh[0], p0.y, my);
        fine_add(sh[0], p0.z, mz); fine_add(sh[0], p0.w, mw);
        fine_add(sh[1], p1.x, mx); fine_add(sh[1], p1.y, my);
        fine_add(sh[1], p1.z, mz); fine_add(sh[1], p1.w, mw);
        fine_add(sh[2], p2.x, mx); fine_add(sh[2], p2.y, my);
        fine_add(sh[2], p2.z, mz); fine_add(sh[2], p2.w, mw);
        fine_add(sh[3], t0.x, mx); fine_add(sh[3], t0.y, my);
        fine_add(sh[3], t0.z, mz); fine_add(sh[3], t0.w, mw);
        fine_add(sh[4], t1.x, mx); fine_add(sh[4], t1.y, my);
        fine_add(sh[4], t1.z, mz); fine_add(sh[4], t1.w, mw);
        fine_add(sh[5], t2.x, mx); fine_add(sh[5], t2.y, my);
        fine_add(sh[5], t2.z, mz); fine_add(sh[5], t2.w, mw);
    }
    __syncthreads();

    // Flush with 4:1 fold to 256 global bins.  idx -> (ct, jc).
    #pragma unroll
    for (int idx = threadIdx.x; idx < 6 * NFC; idx += HIST_THREADS) {
        int ct = idx >> 8;                               // 0..5 (0-2 pred, 3-5 target)
        int jc = idx & (NFC - 1);
        const unsigned int* cell = &sh[ct][jc << 2];
        unsigned long long cnt = 0, sd = 0;
        #pragma unroll
        for (int r = 0; r < 4; r++) {
            unsigned int v = cell[r];
            unsigned long long c = v >> 18;
            sd  += (unsigned long long)(v & 0x3FFFFu) + 16ull * (unsigned)r * c;
            cnt += c;
        }
        if (cnt) {
            int t  = ct >= 3;
            int ch = ct - t * 3;
            atomicAdd(&g_fine[t * 24 + b * 3 + ch][jc], (cnt << 32) | sd);
        }
    }
}

// ---------------------------------------------------------------------------
// Kernel 2: reconstruct.  One warp per (slice, coarse-bin) task: 768 tasks,
// grid = 96 blocks x 256 threads.  No smem, no barriers, no atomics.
// ---------------------------------------------------------------------------
__global__ __launch_bounds__(256) void reconstruct_kernel() {
    int warp = threadIdx.x >> 5;
    int lane = threadIdx.x & 31;
    int task = blockIdx.x * 8 + warp;                    // 0..767
    int s = task >> 4;                                   // slice
    int k = task & 15;                                   // coarse bin

    const unsigned long long* __restrict__ gf = g_fine[s];
    const float* __restrict__ wr  = g_w [k];
    const float* __restrict__ wpr = g_wp[k];

    float acc = 0.0f;
    #pragma unroll
    for (int r = 0; r < NFC / 32; r++) {                 // 8 independent iterations
        int j = r * 32 + lane;
        unsigned long long v = gf[j];
        float n  = (float)(unsigned)(v >> 32);
        float sd = (float)(unsigned)(v & 0xFFFFFFFFu);   // sum(delta64)
        // sum(delta) ~= (sum(delta64) + 0.5 n)/64 ; sdv = (sum(delta) - n/2) / NFC
        float sdv = (sd * 0.015625f - n * 0.4921875f) * (1.0f / (float)NFC);
        acc = fmaf(n, __ldg(&wr[j]), fmaf(sdv, __ldg(&wpr[j]), acc));
    }
    #pragma unroll
    for (int off = 16; off > 0; off >>= 1)
        acc += __shfl_xor_sync(0xffffffffu, acc, off);
    if (lane == 0) g_hist[s][k] = acc;
}

// ---------------------------------------------------------------------------
// Kernel 3: final loss (all fp32) + re-zero g_fine for the next call.
// 1 block, 512 threads.
// ---------------------------------------------------------------------------
__global__ __launch_bounds__(512) void final_kernel(float* __restrict__ out) {
    int tid = threadIdx.x;

    // self-clean scratch (96 KB)
    unsigned long long* gfall = (unsigned long long*)g_fine;
    #pragma unroll
    for (int i = tid; i < NSLICE * NFC; i += 512) gfall[i] = 0ULL;

    float a = 0.0f;
    if (tid < 24) {
        const float* hp = g_hist[tid];                   // pred slice bc
        const float* ht = g_hist[24 + tid];              // target slice bc
        float s0 = 0.0f, s1 = 0.0f;
        #pragma unroll
        for (int k = 0; k < NB; k++) { s0 += hp[k]; s1 += ht[k]; }
        float i0 = 1.0f / (s0 + 1e-7f);
        float i1 = 1.0f / (s1 + 1e-7f);
        #pragma unroll
        for (int k = 0; k < NB; k++)
            a += fabsf(hp[k] * i0 - ht[k] * i1);
    }
    if (tid < 32) {                                      // warp 0 reduce (lanes 24-31 carry 0)
        #pragma unroll
        for (int off = 16; off > 0; off >>= 1)
            a += __shfl_down_sync(0xffffffffu, a, off);
        if (tid == 0) *out = a * (1.0f / 384.0f);
    }
}

// ---------------------------------------------------------------------------
extern "C" void kernel_launch(void* const* d_in, const int* in_sizes, int n_in,
                              void* d_out, int out_size) {
    const float* pred   = (const float*)d_in[0];
    const float* target = (const float*)d_in[1];
    float* out = (float*)d_out;

    hist_kernel<<<BATCH * SPLITS, HIST_THREADS>>>(pred, target);
    reconstruct_kernel<<<NSLICE * NB / 8, 256>>>();
    final_kernel<<<1, 512>>>(out);
}